// round 5
// baseline (speedup 1.0000x reference)
#include <cuda_runtime.h>
#include <cuda_bf16.h>
#include <cstdint>

// One CTA per batch row b (B=4096), 256 threads, 8 samples/thread (n=2048).
// All samples of a row land in an 8^3 voxel window (|bound_psf|*SCL < 2.52,
// margin 0.02). Window staged in tap-pair float4 layout:
// sv4[(z*7+y)*7+x] = (v[x,y], v[x+1,y], v[x,y+1], v[x+1,y+1]) at depth z;
// trilinear = 2x LDS.128. Inner loop batches 4 samples: 8 LDS issued
// back-to-back (MLP=8) before any consumption.

#define SPAN 8
#define NTHREADS 256
#define SCL (256.0f / 255.0f)
#define NEG_HALF_LOG2E (-0.72134752044448170368f)

__device__ __forceinline__ float tanh_fast(float x) {
    float y;
    asm("tanh.approx.f32 %0, %1;" : "=f"(y) : "f"(x));
    return y;
}

__global__ __launch_bounds__(NTHREADS, 3)
void select_profile_kernel(
    const float* __restrict__ vol,       // [256,256,256]
    const float* __restrict__ sg,        // [B,3]
    const float* __restrict__ ax,        // [B,1,6]
    const float* __restrict__ bound,     // [B,2,3]
    const float* __restrict__ icov,      // [B,3,3]
    const float* __restrict__ xyz,       // [B,n,3]
    float* __restrict__ out,             // [B]
    int n)
{
    __shared__ float4 sv4[SPAN * 7 * 7];               // 6.3 KB
    __shared__ float  rnum[NTHREADS / 32];
    __shared__ float  rden[NTHREADS / 32];

    const int b   = blockIdx.x;
    const int tid = threadIdx.x;

    // ---- prefetch this thread's 8 samples (24 floats = 6 float4) NOW ----
    const int base = tid * 8;
    float4 q0, q1, q2, q3, q4, q5;
    if (base < n) {
        const float4* p4 = (const float4*)(xyz + ((size_t)b * n + base) * 3);
        q0 = __ldcs(p4 + 0); q1 = __ldcs(p4 + 1); q2 = __ldcs(p4 + 2);
        q3 = __ldcs(p4 + 3); q4 = __ldcs(p4 + 4); q5 = __ldcs(p4 + 5);
    } else {
        q0 = q1 = q2 = q3 = q4 = q5 = make_float4(0.f, 0.f, 0.f, 0.f);
    }

    // ---- per-row parameters (redundant per thread; broadcast L1 hits) ----
    const float vx = __ldg(&ax[b * 6 + 0]), vy = __ldg(&ax[b * 6 + 1]), vz = __ldg(&ax[b * 6 + 2]);
    const float Tx = __ldg(&ax[b * 6 + 3]), Ty = __ldg(&ax[b * 6 + 4]), Tz = __ldg(&ax[b * 6 + 5]);

    const float th  = sqrtf(vx * vx + vy * vy + vz * vz + 1e-12f);
    const float itn = 1.0f / th;
    const float kx = vx * itn, ky = vy * itn, kz = vz * itn;
    float s, cth;
    __sincosf(th, &s, &cth);
    const float c = 1.0f - cth;

    const float R00 = 1.0f + c * (kx * kx - 1.0f);
    const float R01 = -s * kz + c * kx * ky;
    const float R02 =  s * ky + c * kx * kz;
    const float R10 =  s * kz + c * kx * ky;
    const float R11 = 1.0f + c * (ky * ky - 1.0f);
    const float R12 = -s * kx + c * ky * kz;
    const float R20 = -s * ky + c * kx * kz;
    const float R21 =  s * kx + c * ky * kz;
    const float R22 = 1.0f + c * (kz * kz - 1.0f);

    const float px = __ldg(&sg[b * 3 + 0]) + Tx;
    const float py = __ldg(&sg[b * 3 + 1]) + Ty;
    const float pz = __ldg(&sg[b * 3 + 2]) + Tz;

    const float cxw = R00 * px + R01 * py + R02 * pz;
    const float cyw = R10 * px + R11 * py + R12 * pz;
    const float czw = R20 * px + R21 * py + R22 * pz;

    const float hx = (__ldg(&bound[b * 6 + 3]) - __ldg(&bound[b * 6 + 0])) * 0.5f;
    const float hy = (__ldg(&bound[b * 6 + 4]) - __ldg(&bound[b * 6 + 1])) * 0.5f;
    const float hz = (__ldg(&bound[b * 6 + 5]) - __ldg(&bound[b * 6 + 2])) * 0.5f;

    const float cx2 = cxw * SCL - 0.5f;
    const float cy2 = cyw * SCL - 0.5f;
    const float cz2 = czw * SCL - 0.5f;

    const int lox = (int)floorf(cx2 - hx * SCL - 0.02f);
    const int loy = (int)floorf(cy2 - hy * SCL - 0.02f);
    const int loz = (int)floorf(cz2 - hz * SCL - 0.02f);

    const float cxl = cx2 - (float)lox;   // window-local center
    const float cyl = cy2 - (float)loy;
    const float czl = cz2 - (float)loz;

    // quadratic form, pre-scaled by -0.5*log2(e) so w = exp2f(q)
    const float* M = icov + (size_t)b * 9;
    const float M00 = __ldg(M + 0) * NEG_HALF_LOG2E;
    const float M11 = __ldg(M + 4) * NEG_HALF_LOG2E;
    const float M22 = __ldg(M + 8) * NEG_HALF_LOG2E;
    const float S01 = (__ldg(M + 1) + __ldg(M + 3)) * NEG_HALF_LOG2E;
    const float S02 = (__ldg(M + 2) + __ldg(M + 6)) * NEG_HALF_LOG2E;
    const float S12 = (__ldg(M + 5) + __ldg(M + 7)) * NEG_HALF_LOG2E;

    // ---- stage tap-pair window; uniform interior fast path ----
    // NOTE: scalar __ldg only — (lox+x) has arbitrary parity, so float2
    // loads at vol+rbase would be 4B-aligned -> misaligned-address trap.
    const bool interior = (lox >= 0) && (lox <= 248) &&
                          (loy >= 0) && (loy <= 248) &&
                          (loz >= 0) && (loz <= 248);
    if (interior) {
        #pragma unroll
        for (int idx = tid; idx < SPAN * 7 * 7; idx += NTHREADS) {
            const int x = idx % 7;
            const int zy = idx / 7;
            const int y = zy % 7;
            const int z = zy / 7;
            const size_t rbase = ((size_t)(loz + z) * 256 + (loy + y)) * 256 + (lox + x);
            sv4[idx] = make_float4(__ldg(vol + rbase),
                                   __ldg(vol + rbase + 1),
                                   __ldg(vol + rbase + 256),
                                   __ldg(vol + rbase + 257));
        }
    } else {
        #pragma unroll
        for (int idx = tid; idx < SPAN * 7 * 7; idx += NTHREADS) {
            const int x = idx % 7;
            const int zy = idx / 7;
            const int y = zy % 7;
            const int z = zy / 7;
            const int xg = lox + x, yg = loy + y, zg = loz + z;
            const bool zin = (unsigned)zg < 256u;
            const bool x0in = (unsigned)xg < 256u;
            const bool x1in = (unsigned)(xg + 1) < 256u;
            const bool y0in = (unsigned)yg < 256u;
            const bool y1in = (unsigned)(yg + 1) < 256u;
            const size_t rbase = ((size_t)zg * 256 + yg) * 256 + xg;
            float4 t = make_float4(0.f, 0.f, 0.f, 0.f);
            if (zin) {
                if (x0in && y0in) t.x = __ldg(vol + rbase);
                if (x1in && y0in) t.y = __ldg(vol + rbase + 1);
                if (x0in && y1in) t.z = __ldg(vol + rbase + 256);
                if (x1in && y1in) t.w = __ldg(vol + rbase + 257);
            }
            sv4[idx] = t;
        }
    }
    __syncthreads();

    float num = 0.0f, den = 0.0f;

    if (base < n) {
        const float bufx[8] = { q0.x, q0.w, q1.z, q2.y, q3.x, q3.w, q4.z, q5.y };
        const float bufy[8] = { q0.y, q1.x, q1.w, q2.z, q3.y, q4.x, q4.w, q5.z };
        const float bufz[8] = { q0.z, q1.y, q2.x, q2.w, q3.z, q4.y, q5.x, q5.w };

        #pragma unroll
        for (int g = 0; g < 2; g++) {       // two batches of 4 samples
            float bx[4], by[4], bz[4], fx[4], fy[4], fz[4];
            int   bi[4];

            #pragma unroll
            for (int j = 0; j < 4; j++) {
                const int i = g * 4 + j;
                bx[j] = tanh_fast(0.5f * bufx[i]) * hx;
                by[j] = tanh_fast(0.5f * bufy[i]) * hy;
                bz[j] = tanh_fast(0.5f * bufz[i]) * hz;
                const float lxf = fmaf(bx[j], SCL, cxl);
                const float lyf = fmaf(by[j], SCL, cyl);
                const float lzf = fmaf(bz[j], SCL, czl);
                const float x0f = floorf(lxf);
                const float y0f = floorf(lyf);
                const float z0f = floorf(lzf);
                fx[j] = lxf - x0f;
                fy[j] = lyf - y0f;
                fz[j] = lzf - z0f;
                bi[j] = (int)fmaf(fmaf(z0f, 7.0f, y0f), 7.0f, x0f);
            }

            // issue all 8 LDS.128 back-to-back (MLP=8)
            float4 a0[4], a1[4];
            #pragma unroll
            for (int j = 0; j < 4; j++) {
                a0[j] = sv4[bi[j]];
                a1[j] = sv4[bi[j] + 49];
            }

            #pragma unroll
            for (int j = 0; j < 4; j++) {
                const float c00 = fmaf(fx[j], a0[j].y - a0[j].x, a0[j].x);
                const float c01 = fmaf(fx[j], a0[j].w - a0[j].z, a0[j].z);
                const float c10 = fmaf(fx[j], a1[j].y - a1[j].x, a1[j].x);
                const float c11 = fmaf(fx[j], a1[j].w - a1[j].z, a1[j].z);
                const float c0  = fmaf(fy[j], c01 - c00, c00);
                const float c1  = fmaf(fy[j], c11 - c10, c10);
                const float pv  = fmaf(fz[j], c1 - c0, c0);

                const float t1 = fmaf(M00, bx[j], fmaf(S01, by[j], S02 * bz[j]));
                const float t2 = fmaf(M11, by[j], S12 * bz[j]);
                const float qf = fmaf(bx[j], t1, fmaf(by[j], t2, bz[j] * (M22 * bz[j])));
                const float w  = exp2f(qf);

                num = fmaf(pv, w, num);
                den += w;
            }
        }
    }

    // general-n fallback (no-op for n = 2048)
    for (int bb = NTHREADS * 8 + tid * 8; bb < n; bb += NTHREADS * 8) {
        const float4* p4 = (const float4*)(xyz + ((size_t)b * n + bb) * 3);
        float4 r0 = __ldcs(p4 + 0), r1 = __ldcs(p4 + 1), r2 = __ldcs(p4 + 2),
               r3 = __ldcs(p4 + 3), r4 = __ldcs(p4 + 4), r5 = __ldcs(p4 + 5);
        const float bufa[24] = { r0.x, r0.y, r0.z, r0.w, r1.x, r1.y, r1.z, r1.w,
                                 r2.x, r2.y, r2.z, r2.w, r3.x, r3.y, r3.z, r3.w,
                                 r4.x, r4.y, r4.z, r4.w, r5.x, r5.y, r5.z, r5.w };
        #pragma unroll
        for (int i = 0; i < 8; i++) {
            const float bx = tanh_fast(0.5f * bufa[3 * i + 0]) * hx;
            const float by = tanh_fast(0.5f * bufa[3 * i + 1]) * hy;
            const float bz = tanh_fast(0.5f * bufa[3 * i + 2]) * hz;
            const float lxf = fmaf(bx, SCL, cxl);
            const float lyf = fmaf(by, SCL, cyl);
            const float lzf = fmaf(bz, SCL, czl);
            const float x0f = floorf(lxf), y0f = floorf(lyf), z0f = floorf(lzf);
            const float fxs = lxf - x0f, fys = lyf - y0f, fzs = lzf - z0f;
            const int bi = (int)fmaf(fmaf(z0f, 7.0f, y0f), 7.0f, x0f);
            const float4 a0 = sv4[bi];
            const float4 a1 = sv4[bi + 49];
            const float c00 = fmaf(fxs, a0.y - a0.x, a0.x);
            const float c01 = fmaf(fxs, a0.w - a0.z, a0.z);
            const float c10 = fmaf(fxs, a1.y - a1.x, a1.x);
            const float c11 = fmaf(fxs, a1.w - a1.z, a1.z);
            const float c0  = fmaf(fys, c01 - c00, c00);
            const float c1  = fmaf(fys, c11 - c10, c10);
            const float pv  = fmaf(fzs, c1 - c0, c0);
            const float t1 = fmaf(M00, bx, fmaf(S01, by, S02 * bz));
            const float t2 = fmaf(M11, by, S12 * bz);
            const float qf = fmaf(bx, t1, fmaf(by, t2, bz * (M22 * bz)));
            const float w  = exp2f(qf);
            num = fmaf(pv, w, num);
            den += w;
        }
    }

    // ---- reduction ----
    #pragma unroll
    for (int o = 16; o > 0; o >>= 1) {
        num += __shfl_xor_sync(0xFFFFFFFFu, num, o);
        den += __shfl_xor_sync(0xFFFFFFFFu, den, o);
    }
    if ((tid & 31) == 0) {
        rnum[tid >> 5] = num;
        rden[tid >> 5] = den;
    }
    __syncthreads();
    if (tid == 0) {
        float N = 0.0f, Dn = 0.0f;
        #pragma unroll
        for (int i = 0; i < NTHREADS / 32; i++) { N += rnum[i]; Dn += rden[i]; }
        out[b] = N / Dn;
    }
}

extern "C" void kernel_launch(void* const* d_in, const int* in_sizes, int n_in,
                              void* d_out, int out_size) {
    const float* vol   = (const float*)d_in[0];  // x [1,1,256,256,256]
    const float* sg    = (const float*)d_in[1];  // sampleGrid [B,3]
    const float* ax    = (const float*)d_in[2];  // ax [B,1,6]
    const float* bound = (const float*)d_in[3];  // bound [B,2,3]
    const float* icov  = (const float*)d_in[4];  // InvCovScaled [B,3,3]
    // d_in[5] = psf_sigma (unused by reference)
    const float* xyz   = (const float*)d_in[6];  // xyz_psf [B,n,3]
    float* out = (float*)d_out;

    const int B = in_sizes[1] / 3;
    const int n = in_sizes[6] / (B * 3);

    select_profile_kernel<<<B, NTHREADS>>>(vol, sg, ax, bound, icov, xyz, out, n);
}

// round 6
// speedup vs baseline: 1.1758x; 1.1758x over previous
#include <cuda_runtime.h>
#include <cuda_bf16.h>
#include <cstdint>

// One CTA per batch row b (B=4096), 256 threads, 8 samples/thread (n=2048).
// All samples of a row land in an 8^3 voxel window (|bound_psf|*SCL < 2.52,
// margin 0.02). Window staged in tap-pair float4 layout:
//   sv4[(z*7+y)*7+x] = (v[x,y], v[x+1,y], v[x,y+1], v[x+1,y+1]) at depth z
// so trilinear = 2x LDS.128. Occupancy-first: regs capped, sequential
// samples, one barrier, no register-hungry pipelining.

#define SPAN 8
#define NTHREADS 256
#define SPT 8
#define SCL (256.0f / 255.0f)
#define NEG_HALF_LOG2E (-0.72134752044448170368f)

__device__ __forceinline__ float tanh_fast(float x) {
    float y;
    asm("tanh.approx.f32 %0, %1;" : "=f"(y) : "f"(x));
    return y;
}

__global__ __launch_bounds__(NTHREADS, 5)
void select_profile_kernel(
    const float* __restrict__ vol,       // [256,256,256]
    const float* __restrict__ sg,        // [B,3]
    const float* __restrict__ ax,        // [B,1,6]
    const float* __restrict__ bound,     // [B,2,3]
    const float* __restrict__ icov,      // [B,3,3]
    const float* __restrict__ xyz,       // [B,n,3]
    float* __restrict__ out,             // [B]
    int n)
{
    __shared__ float4 sv4[SPAN * 7 * 7];               // 6.3 KB
    __shared__ float  rnum[NTHREADS / 32];
    __shared__ float  rden[NTHREADS / 32];

    const int b   = blockIdx.x;
    const int tid = threadIdx.x;

    // ---- per-row parameters (redundant per thread; broadcast L1 hits) ----
    const float vx = __ldg(&ax[b * 6 + 0]), vy = __ldg(&ax[b * 6 + 1]), vz = __ldg(&ax[b * 6 + 2]);
    const float Tx = __ldg(&ax[b * 6 + 3]), Ty = __ldg(&ax[b * 6 + 4]), Tz = __ldg(&ax[b * 6 + 5]);

    const float th  = sqrtf(vx * vx + vy * vy + vz * vz + 1e-12f);
    const float itn = 1.0f / th;
    const float kx = vx * itn, ky = vy * itn, kz = vz * itn;
    float s, cth;
    __sincosf(th, &s, &cth);
    const float c = 1.0f - cth;

    const float R00 = 1.0f + c * (kx * kx - 1.0f);
    const float R01 = -s * kz + c * kx * ky;
    const float R02 =  s * ky + c * kx * kz;
    const float R10 =  s * kz + c * kx * ky;
    const float R11 = 1.0f + c * (ky * ky - 1.0f);
    const float R12 = -s * kx + c * ky * kz;
    const float R20 = -s * ky + c * kx * kz;
    const float R21 =  s * kx + c * ky * kz;
    const float R22 = 1.0f + c * (kz * kz - 1.0f);

    const float px = __ldg(&sg[b * 3 + 0]) + Tx;
    const float py = __ldg(&sg[b * 3 + 1]) + Ty;
    const float pz = __ldg(&sg[b * 3 + 2]) + Tz;

    const float cxw = R00 * px + R01 * py + R02 * pz;
    const float cyw = R10 * px + R11 * py + R12 * pz;
    const float czw = R20 * px + R21 * py + R22 * pz;

    const float hx = (__ldg(&bound[b * 6 + 3]) - __ldg(&bound[b * 6 + 0])) * 0.5f;
    const float hy = (__ldg(&bound[b * 6 + 4]) - __ldg(&bound[b * 6 + 1])) * 0.5f;
    const float hz = (__ldg(&bound[b * 6 + 5]) - __ldg(&bound[b * 6 + 2])) * 0.5f;

    const float cx2 = cxw * SCL - 0.5f;
    const float cy2 = cyw * SCL - 0.5f;
    const float cz2 = czw * SCL - 0.5f;

    const int lox = (int)floorf(cx2 - hx * SCL - 0.02f);
    const int loy = (int)floorf(cy2 - hy * SCL - 0.02f);
    const int loz = (int)floorf(cz2 - hz * SCL - 0.02f);

    const float cxl = cx2 - (float)lox;   // window-local center
    const float cyl = cy2 - (float)loy;
    const float czl = cz2 - (float)loz;

    // quadratic form, pre-scaled by -0.5*log2(e) so w = exp2f(q)
    const float* M = icov + (size_t)b * 9;
    const float M00 = __ldg(M + 0) * NEG_HALF_LOG2E;
    const float M11 = __ldg(M + 4) * NEG_HALF_LOG2E;
    const float M22 = __ldg(M + 8) * NEG_HALF_LOG2E;
    const float S01 = (__ldg(M + 1) + __ldg(M + 3)) * NEG_HALF_LOG2E;
    const float S02 = (__ldg(M + 2) + __ldg(M + 6)) * NEG_HALF_LOG2E;
    const float S12 = (__ldg(M + 5) + __ldg(M + 7)) * NEG_HALF_LOG2E;

    // ---- stage tap-pair window (scalar __ldg only; alignment!) ----
    const bool interior = (lox >= 0) && (lox <= 248) &&
                          (loy >= 0) && (loy <= 248) &&
                          (loz >= 0) && (loz <= 248);
    if (interior) {
        #pragma unroll
        for (int idx = tid; idx < SPAN * 7 * 7; idx += NTHREADS) {
            const int x = idx % 7;
            const int zy = idx / 7;
            const int y = zy % 7;
            const int z = zy / 7;
            const size_t rbase = ((size_t)(loz + z) * 256 + (loy + y)) * 256 + (lox + x);
            sv4[idx] = make_float4(__ldg(vol + rbase),
                                   __ldg(vol + rbase + 1),
                                   __ldg(vol + rbase + 256),
                                   __ldg(vol + rbase + 257));
        }
    } else {
        #pragma unroll
        for (int idx = tid; idx < SPAN * 7 * 7; idx += NTHREADS) {
            const int x = idx % 7;
            const int zy = idx / 7;
            const int y = zy % 7;
            const int z = zy / 7;
            const int xg = lox + x, yg = loy + y, zg = loz + z;
            const bool zin = (unsigned)zg < 256u;
            const bool x0in = (unsigned)xg < 256u;
            const bool x1in = (unsigned)(xg + 1) < 256u;
            const bool y0in = (unsigned)yg < 256u;
            const bool y1in = (unsigned)(yg + 1) < 256u;
            const size_t rbase = ((size_t)zg * 256 + yg) * 256 + xg;
            float4 t = make_float4(0.f, 0.f, 0.f, 0.f);
            if (zin) {
                if (x0in && y0in) t.x = __ldg(vol + rbase);
                if (x1in && y0in) t.y = __ldg(vol + rbase + 1);
                if (x0in && y1in) t.z = __ldg(vol + rbase + 256);
                if (x1in && y1in) t.w = __ldg(vol + rbase + 257);
            }
            sv4[idx] = t;
        }
    }
    __syncthreads();

    float num = 0.0f, den = 0.0f;

    for (int i0 = tid * SPT; i0 < n; i0 += NTHREADS * SPT) {
        const float4* p4 = (const float4*)(xyz + ((size_t)b * n + i0) * 3);

        #pragma unroll
        for (int g = 0; g < SPT / 4; g++) {
            // 4 samples = 12 floats = 3 aligned float4
            const float4 r0 = __ldcs(p4 + g * 3 + 0);
            const float4 r1 = __ldcs(p4 + g * 3 + 1);
            const float4 r2 = __ldcs(p4 + g * 3 + 2);
            const float sx[4] = { r0.x, r0.w, r1.z, r2.y };
            const float sy[4] = { r0.y, r1.x, r1.w, r2.z };
            const float sz[4] = { r0.z, r1.y, r2.x, r2.w };

            #pragma unroll
            for (int j = 0; j < 4; j++) {
                // 2*sigmoid(t) - 1 = tanh(t/2)
                const float bx = tanh_fast(0.5f * sx[j]) * hx;
                const float by = tanh_fast(0.5f * sy[j]) * hy;
                const float bz = tanh_fast(0.5f * sz[j]) * hz;

                const float lxf = fmaf(bx, SCL, cxl);
                const float lyf = fmaf(by, SCL, cyl);
                const float lzf = fmaf(bz, SCL, czl);

                const float x0f = floorf(lxf);
                const float y0f = floorf(lyf);
                const float z0f = floorf(lzf);
                const float fx = lxf - x0f;
                const float fy = lyf - y0f;
                const float fz = lzf - z0f;

                const int bi = (int)fmaf(fmaf(z0f, 7.0f, y0f), 7.0f, x0f);
                const float4 a0 = sv4[bi];        // z0  : v000 v001 v010 v011
                const float4 a1 = sv4[bi + 49];   // z0+1: v100 v101 v110 v111

                const float c00 = fmaf(fx, a0.y - a0.x, a0.x);
                const float c01 = fmaf(fx, a0.w - a0.z, a0.z);
                const float c10 = fmaf(fx, a1.y - a1.x, a1.x);
                const float c11 = fmaf(fx, a1.w - a1.z, a1.z);
                const float c0  = fmaf(fy, c01 - c00, c00);
                const float c1  = fmaf(fy, c11 - c10, c10);
                const float pv  = fmaf(fz, c1 - c0, c0);

                const float t1 = fmaf(M00, bx, fmaf(S01, by, S02 * bz));
                const float t2 = fmaf(M11, by, S12 * bz);
                const float qf = fmaf(bx, t1, fmaf(by, t2, bz * (M22 * bz)));
                const float w  = exp2f(qf);

                num = fmaf(pv, w, num);
                den += w;
            }
        }
    }

    // ---- reduction ----
    #pragma unroll
    for (int o = 16; o > 0; o >>= 1) {
        num += __shfl_xor_sync(0xFFFFFFFFu, num, o);
        den += __shfl_xor_sync(0xFFFFFFFFu, den, o);
    }
    if ((tid & 31) == 0) {
        rnum[tid >> 5] = num;
        rden[tid >> 5] = den;
    }
    __syncthreads();
    if (tid == 0) {
        float N = 0.0f, Dn = 0.0f;
        #pragma unroll
        for (int i = 0; i < NTHREADS / 32; i++) { N += rnum[i]; Dn += rden[i]; }
        out[b] = N / Dn;
    }
}

extern "C" void kernel_launch(void* const* d_in, const int* in_sizes, int n_in,
                              void* d_out, int out_size) {
    const float* vol   = (const float*)d_in[0];  // x [1,1,256,256,256]
    const float* sg    = (const float*)d_in[1];  // sampleGrid [B,3]
    const float* ax    = (const float*)d_in[2];  // ax [B,1,6]
    const float* bound = (const float*)d_in[3];  // bound [B,2,3]
    const float* icov  = (const float*)d_in[4];  // InvCovScaled [B,3,3]
    // d_in[5] = psf_sigma (unused by reference)
    const float* xyz   = (const float*)d_in[6];  // xyz_psf [B,n,3]
    float* out = (float*)d_out;

    const int B = in_sizes[1] / 3;
    const int n = in_sizes[6] / (B * 3);

    select_profile_kernel<<<B, NTHREADS>>>(vol, sg, ax, bound, icov, xyz, out, n);
}

// round 8
// speedup vs baseline: 1.3806x; 1.1741x over previous
#include <cuda_runtime.h>
#include <cuda_fp16.h>
#include <cuda_bf16.h>
#include <cstdint>

// One CTA per batch row b (B=4096), 256 threads, 8 samples/thread (n=2048).
// All samples of a row land in an 8^3 voxel window (|bound_psf|*SCL < 2.52,
// margin 0.02). Window staged in fp16 tap-pair layout:
//   svh[(z*7+y)*7+x] = half4(v[x,y], v[x+1,y], v[x,y+1], v[x+1,y+1]) at depth z
// so trilinear = 2x LDS.64 (16 B/sample on the crossbar, half of fp32 taps).
// Interp math in fp32 after F2F converts.

#define SPAN 8
#define NTHREADS 256
#define SPT 8
#define SCL (256.0f / 255.0f)
#define NEG_HALF_LOG2E (-0.72134752044448170368f)

__device__ __forceinline__ float tanh_fast(float x) {
    float y;
    asm("tanh.approx.f32 %0, %1;" : "=f"(y) : "f"(x));
    return y;
}

__global__ __launch_bounds__(NTHREADS, 5)
void select_profile_kernel(
    const float* __restrict__ vol,       // [256,256,256]
    const float* __restrict__ sg,        // [B,3]
    const float* __restrict__ ax,        // [B,1,6]
    const float* __restrict__ bound,     // [B,2,3]
    const float* __restrict__ icov,      // [B,3,3]
    const float* __restrict__ xyz,       // [B,n,3]
    float* __restrict__ out,             // [B]
    int n)
{
    __shared__ uint2 svh[SPAN * 7 * 7];                // 3.1 KB (fp16 tap pairs)
    __shared__ float rnum[NTHREADS / 32];
    __shared__ float rden[NTHREADS / 32];

    const int b   = blockIdx.x;
    const int tid = threadIdx.x;

    // ---- per-row parameters (redundant per thread; broadcast L1 hits) ----
    const float vx = __ldg(&ax[b * 6 + 0]), vy = __ldg(&ax[b * 6 + 1]), vz = __ldg(&ax[b * 6 + 2]);
    const float Tx = __ldg(&ax[b * 6 + 3]), Ty = __ldg(&ax[b * 6 + 4]), Tz = __ldg(&ax[b * 6 + 5]);

    const float th  = sqrtf(vx * vx + vy * vy + vz * vz + 1e-12f);
    const float itn = 1.0f / th;
    const float kx = vx * itn, ky = vy * itn, kz = vz * itn;
    float s, cth;
    __sincosf(th, &s, &cth);
    const float c = 1.0f - cth;

    const float R00 = 1.0f + c * (kx * kx - 1.0f);
    const float R01 = -s * kz + c * kx * ky;
    const float R02 =  s * ky + c * kx * kz;
    const float R10 =  s * kz + c * kx * ky;
    const float R11 = 1.0f + c * (ky * ky - 1.0f);
    const float R12 = -s * kx + c * ky * kz;
    const float R20 = -s * ky + c * kx * kz;
    const float R21 =  s * kx + c * ky * kz;
    const float R22 = 1.0f + c * (kz * kz - 1.0f);

    const float px = __ldg(&sg[b * 3 + 0]) + Tx;
    const float py = __ldg(&sg[b * 3 + 1]) + Ty;
    const float pz = __ldg(&sg[b * 3 + 2]) + Tz;

    const float cxw = R00 * px + R01 * py + R02 * pz;
    const float cyw = R10 * px + R11 * py + R12 * pz;
    const float czw = R20 * px + R21 * py + R22 * pz;

    const float hx = (__ldg(&bound[b * 6 + 3]) - __ldg(&bound[b * 6 + 0])) * 0.5f;
    const float hy = (__ldg(&bound[b * 6 + 4]) - __ldg(&bound[b * 6 + 1])) * 0.5f;
    const float hz = (__ldg(&bound[b * 6 + 5]) - __ldg(&bound[b * 6 + 2])) * 0.5f;

    const float cx2 = cxw * SCL - 0.5f;
    const float cy2 = cyw * SCL - 0.5f;
    const float cz2 = czw * SCL - 0.5f;

    const int lox = (int)floorf(cx2 - hx * SCL - 0.02f);
    const int loy = (int)floorf(cy2 - hy * SCL - 0.02f);
    const int loz = (int)floorf(cz2 - hz * SCL - 0.02f);

    const float cxl = cx2 - (float)lox;   // window-local center
    const float cyl = cy2 - (float)loy;
    const float czl = cz2 - (float)loz;

    // coordinate scale folded: lxf = u * hxS + cxl, u = tanh(0.5*s)
    const float hxS = hx * SCL, hyS = hy * SCL, hzS = hz * SCL;

    // quadratic form in terms of u (h folded in), pre-scaled by -0.5*log2(e)
    const float* M = icov + (size_t)b * 9;
    const float M00 = __ldg(M + 0) * NEG_HALF_LOG2E * hx * hx;
    const float M11 = __ldg(M + 4) * NEG_HALF_LOG2E * hy * hy;
    const float M22 = __ldg(M + 8) * NEG_HALF_LOG2E * hz * hz;
    const float S01 = (__ldg(M + 1) + __ldg(M + 3)) * NEG_HALF_LOG2E * hx * hy;
    const float S02 = (__ldg(M + 2) + __ldg(M + 6)) * NEG_HALF_LOG2E * hx * hz;
    const float S12 = (__ldg(M + 5) + __ldg(M + 7)) * NEG_HALF_LOG2E * hy * hz;

    // ---- stage fp16 tap-pair window (scalar __ldg; alignment!) ----
    const bool interior = (lox >= 0) && (lox <= 248) &&
                          (loy >= 0) && (loy <= 248) &&
                          (loz >= 0) && (loz <= 248);
    if (interior) {
        #pragma unroll
        for (int idx = tid; idx < SPAN * 7 * 7; idx += NTHREADS) {
            const int x = idx % 7;
            const int zy = idx / 7;
            const int y = zy % 7;
            const int z = zy / 7;
            const size_t rbase = ((size_t)(loz + z) * 256 + (loy + y)) * 256 + (lox + x);
            const __half2 lo = __floats2half2_rn(__ldg(vol + rbase),       __ldg(vol + rbase + 1));
            const __half2 hi = __floats2half2_rn(__ldg(vol + rbase + 256), __ldg(vol + rbase + 257));
            uint2 packed;
            packed.x = *(const unsigned int*)&lo;
            packed.y = *(const unsigned int*)&hi;
            svh[idx] = packed;
        }
    } else {
        #pragma unroll
        for (int idx = tid; idx < SPAN * 7 * 7; idx += NTHREADS) {
            const int x = idx % 7;
            const int zy = idx / 7;
            const int y = zy % 7;
            const int z = zy / 7;
            const int xg = lox + x, yg = loy + y, zg = loz + z;
            const bool zin = (unsigned)zg < 256u;
            const bool x0in = (unsigned)xg < 256u;
            const bool x1in = (unsigned)(xg + 1) < 256u;
            const bool y0in = (unsigned)yg < 256u;
            const bool y1in = (unsigned)(yg + 1) < 256u;
            const size_t rbase = ((size_t)zg * 256 + yg) * 256 + xg;
            float v00 = 0.f, v01 = 0.f, v10 = 0.f, v11 = 0.f;
            if (zin) {
                if (x0in && y0in) v00 = __ldg(vol + rbase);
                if (x1in && y0in) v01 = __ldg(vol + rbase + 1);
                if (x0in && y1in) v10 = __ldg(vol + rbase + 256);
                if (x1in && y1in) v11 = __ldg(vol + rbase + 257);
            }
            const __half2 lo = __floats2half2_rn(v00, v01);
            const __half2 hi = __floats2half2_rn(v10, v11);
            uint2 packed;
            packed.x = *(const unsigned int*)&lo;
            packed.y = *(const unsigned int*)&hi;
            svh[idx] = packed;
        }
    }
    __syncthreads();

    float num = 0.0f, den = 0.0f;

    for (int i0 = tid * SPT; i0 < n; i0 += NTHREADS * SPT) {
        const float4* p4 = (const float4*)(xyz + ((size_t)b * n + i0) * 3);

        #pragma unroll
        for (int g = 0; g < SPT / 4; g++) {
            // 4 samples = 12 floats = 3 aligned float4
            const float4 r0 = __ldcs(p4 + g * 3 + 0);
            const float4 r1 = __ldcs(p4 + g * 3 + 1);
            const float4 r2 = __ldcs(p4 + g * 3 + 2);
            const float sx[4] = { r0.x, r0.w, r1.z, r2.y };
            const float sy[4] = { r0.y, r1.x, r1.w, r2.z };
            const float sz[4] = { r0.z, r1.y, r2.x, r2.w };

            #pragma unroll
            for (int j = 0; j < 4; j++) {
                // u = 2*sigmoid(t) - 1 = tanh(t/2), unitless in [-1,1]
                const float ux = tanh_fast(0.5f * sx[j]);
                const float uy = tanh_fast(0.5f * sy[j]);
                const float uz = tanh_fast(0.5f * sz[j]);

                const float lxf = fmaf(ux, hxS, cxl);
                const float lyf = fmaf(uy, hyS, cyl);
                const float lzf = fmaf(uz, hzS, czl);

                const float x0f = floorf(lxf);
                const float y0f = floorf(lyf);
                const float z0f = floorf(lzf);
                const float fx = lxf - x0f;
                const float fy = lyf - y0f;
                const float fz = lzf - z0f;

                const int bi = (int)fmaf(fmaf(z0f, 7.0f, y0f), 7.0f, x0f);

                // two LDS.64, issued back-to-back
                const uint2 t0 = svh[bi];         // z0  : (v000,v001),(v010,v011)
                const uint2 t1 = svh[bi + 49];    // z0+1: (v100,v101),(v110,v111)

                const float2 f00 = __half22float2(*(const __half2*)&t0.x);
                const float2 f01 = __half22float2(*(const __half2*)&t0.y);
                const float2 f10 = __half22float2(*(const __half2*)&t1.x);
                const float2 f11 = __half22float2(*(const __half2*)&t1.y);

                const float c00 = fmaf(fx, f00.y - f00.x, f00.x);
                const float c01 = fmaf(fx, f01.y - f01.x, f01.x);
                const float c10 = fmaf(fx, f10.y - f10.x, f10.x);
                const float c11 = fmaf(fx, f11.y - f11.x, f11.x);
                const float c0  = fmaf(fy, c01 - c00, c00);
                const float c1  = fmaf(fy, c11 - c10, c10);
                const float pv  = fmaf(fz, c1 - c0, c0);

                const float t1q = fmaf(M00, ux, fmaf(S01, uy, S02 * uz));
                const float t2q = fmaf(M11, uy, S12 * uz);
                const float qf  = fmaf(ux, t1q, fmaf(uy, t2q, uz * (M22 * uz)));
                const float w   = exp2f(qf);

                num = fmaf(pv, w, num);
                den += w;
            }
        }
    }

    // ---- reduction ----
    #pragma unroll
    for (int o = 16; o > 0; o >>= 1) {
        num += __shfl_xor_sync(0xFFFFFFFFu, num, o);
        den += __shfl_xor_sync(0xFFFFFFFFu, den, o);
    }
    if ((tid & 31) == 0) {
        rnum[tid >> 5] = num;
        rden[tid >> 5] = den;
    }
    __syncthreads();
    if (tid == 0) {
        float N = 0.0f, Dn = 0.0f;
        #pragma unroll
        for (int i = 0; i < NTHREADS / 32; i++) { N += rnum[i]; Dn += rden[i]; }
        out[b] = N / Dn;
    }
}

extern "C" void kernel_launch(void* const* d_in, const int* in_sizes, int n_in,
                              void* d_out, int out_size) {
    const float* vol   = (const float*)d_in[0];  // x [1,1,256,256,256]
    const float* sg    = (const float*)d_in[1];  // sampleGrid [B,3]
    const float* ax    = (const float*)d_in[2];  // ax [B,1,6]
    const float* bound = (const float*)d_in[3];  // bound [B,2,3]
    const float* icov  = (const float*)d_in[4];  // InvCovScaled [B,3,3]
    // d_in[5] = psf_sigma (unused by reference)
    const float* xyz   = (const float*)d_in[6];  // xyz_psf [B,n,3]
    float* out = (float*)d_out;

    const int B = in_sizes[1] / 3;
    const int n = in_sizes[6] / (B * 3);

    select_profile_kernel<<<B, NTHREADS>>>(vol, sg, ax, bound, icov, xyz, out, n);
}